// round 13
// baseline (speedup 1.0000x reference)
#include <cuda_runtime.h>

// CrossAttention_47502338294587 — algebraic collapse:
// out[b,t,:] = ((vf @ Wv + bv) @ Wp + bp)[b,:]  (K/V broadcast over T ->
// uniform softmax -> y == v; independent of x, Wq, Wk).
//
// R1-R11 invariant: total ~= 8MB weight reads at ~560GB/s env rate + slop;
// steady-state matches COLD ncu timings => replays behave L2-cold despite a
// 25MB working set in a 126MB L2. Test (with legal instructions this time):
//   - output stores via __stcs (streaming / evict-first-ish; 16.8MB/replay
//     stream stops displacing weight lines)
//   - weights touched LAST with prefetch.global.L2::evict_last (scalar form,
//     no vector-shape restriction) so the retained priority is "keep".
// Structure = R3's best-measured 14.8us pipeline: KSPLIT=4, 128-CTA gemms,
// front-batched LDG.128, 3 launches, launch boundaries as syncs, no atomics.

static constexpr int C  = 1024;
static constexpr int B  = 4;
static constexpr int T  = 1024;
static constexpr int KS = 4;          // k-splits: 256 k-rows per CTA

__device__ float g_part1[KS * B * C];   // 64 KB (L2-resident)
__device__ float g_part2[KS * B * C];   // 64 KB

// Mark a weight line "evict last" in L2 (scalar prefetch: legal on sm_103a).
__device__ __forceinline__ void l2_keep(const void* p)
{
    asm volatile("prefetch.global.L2::evict_last [%0];" :: "l"(p));
}

// ---------------- K1: partials of vf @ Wv ----------------
// grid (32 cg, 4 ks) = 128 CTAs; thread (f4 = t&7, kr = t>>3).
__global__ void __launch_bounds__(256) gemm_a(
    const float* __restrict__ vf,     // [B][C]
    const float* __restrict__ W,      // [C][C]
    float* __restrict__ part)         // [KS][B][C]
{
    __shared__ float  s_in[B][256];   // 4 KB
    __shared__ float4 s_red[256][B];  // 16 KB

    const int t  = threadIdx.x;
    const int f4 = t & 7;
    const int kr = t >> 3;            // 0..31
    const int cg = blockIdx.x;        // 0..31
    const int ks = blockIdx.y;        // 0..3
    const int k0 = ks * 256;

    // 8 independent full-line LDG.128, front-batched
    const float4* W4 = (const float4*)W;
    float4 w[8];
    #pragma unroll
    for (int i = 0; i < 8; i++)
        w[i] = W4[(size_t)(k0 + kr + 32 * i) * 256 + cg * 8 + f4];

    #pragma unroll
    for (int i = 0; i < 4; i++) {     // stage vf k-tile (1024 values)
        const int e = t + 256 * i;    // e = b*256 + kk
        s_in[e >> 8][e & 255] = vf[(e >> 8) * C + k0 + (e & 255)];
    }
    __syncthreads();

    #pragma unroll
    for (int b = 0; b < B; b++) {
        float4 a = make_float4(0.f, 0.f, 0.f, 0.f);
        #pragma unroll
        for (int i = 0; i < 8; i++) {
            const float s = s_in[b][kr + 32 * i];
            a.x = fmaf(s, w[i].x, a.x);
            a.y = fmaf(s, w[i].y, a.y);
            a.z = fmaf(s, w[i].z, a.z);
            a.w = fmaf(s, w[i].w, a.w);
        }
        s_red[t][b] = a;
    }

    // Touch weight lines LAST with keep-priority (for future replays).
    #pragma unroll
    for (int i = 0; i < 8; i++)
        l2_keep(&W4[(size_t)(k0 + kr + 32 * i) * 256 + cg * 8 + f4]);
    __syncthreads();

    #pragma unroll
    for (int off = 16; off > 0; off >>= 1) {     // reduce over kr
        if (kr < off) {
            #pragma unroll
            for (int b = 0; b < B; b++) {
                float4 a = s_red[t][b];
                const float4 o = s_red[t + off * 8][b];
                a.x += o.x; a.y += o.y; a.z += o.z; a.w += o.w;
                s_red[t][b] = a;
            }
        }
        __syncthreads();
    }

    if (t < 8) {
        #pragma unroll
        for (int b = 0; b < B; b++)
            ((float4*)part)[(ks * B + b) * 256 + cg * 8 + t] = s_red[t][b];
    }
}

// ------- K2: folds vv = bv + sum(part1); partials of vv @ Wp -------
__global__ void __launch_bounds__(256) gemm_b(
    const float* __restrict__ bv,     // [C]
    const float* __restrict__ W,      // Wp [C][C]
    float* __restrict__ part)         // part2 [KS][B][C]
{
    __shared__ float  s_in[B][256];
    __shared__ float4 s_red[256][B];

    const int t  = threadIdx.x;
    const int f4 = t & 7;
    const int kr = t >> 3;
    const int cg = blockIdx.x;
    const int ks = blockIdx.y;
    const int k0 = ks * 256;

    // Wp loads first, independent of the fold below
    const float4* W4 = (const float4*)W;
    float4 w[8];
    #pragma unroll
    for (int i = 0; i < 8; i++)
        w[i] = W4[(size_t)(k0 + kr + 32 * i) * 256 + cg * 8 + f4];

    #pragma unroll
    for (int i = 0; i < 4; i++) {     // fold vv k-tile: bias + 4 indep loads
        const int e  = t + 256 * i;
        const int b  = e >> 8;
        const int kk = e & 255;
        float v = bv[k0 + kk];
        #pragma unroll
        for (int s = 0; s < KS; s++)
            v += g_part1[(s * B + b) * C + k0 + kk];
        s_in[b][kk] = v;
    }
    __syncthreads();

    #pragma unroll
    for (int b = 0; b < B; b++) {
        float4 a = make_float4(0.f, 0.f, 0.f, 0.f);
        #pragma unroll
        for (int i = 0; i < 8; i++) {
            const float s = s_in[b][kr + 32 * i];
            a.x = fmaf(s, w[i].x, a.x);
            a.y = fmaf(s, w[i].y, a.y);
            a.z = fmaf(s, w[i].z, a.z);
            a.w = fmaf(s, w[i].w, a.w);
        }
        s_red[t][b] = a;
    }

    #pragma unroll
    for (int i = 0; i < 8; i++)       // keep Wp lines across replays
        l2_keep(&W4[(size_t)(k0 + kr + 32 * i) * 256 + cg * 8 + f4]);
    __syncthreads();

    #pragma unroll
    for (int off = 16; off > 0; off >>= 1) {
        if (kr < off) {
            #pragma unroll
            for (int b = 0; b < B; b++) {
                float4 a = s_red[t][b];
                const float4 o = s_red[t + off * 8][b];
                a.x += o.x; a.y += o.y; a.z += o.z; a.w += o.w;
                s_red[t][b] = a;
            }
        }
        __syncthreads();
    }

    if (t < 8) {
        #pragma unroll
        for (int b = 0; b < B; b++)
            ((float4*)part)[(ks * B + b) * 256 + cg * 8 + t] = s_red[t][b];
    }
}

// ------- K3: fold row slice from part2 (+bp), broadcast-write -------
// grid 512 = (b 4) x (cg2 32) x (tq 4); CTA writes 256 rows x 32 cols.
// Output written with __stcs (streaming): don't displace the kept weights.
__global__ void __launch_bounds__(256) bcast_kernel(
    const float* __restrict__ bp, float* __restrict__ out)
{
    __shared__ float s_rowf[32];

    const int t   = threadIdx.x;
    const int f4  = t & 7;
    const int kr  = t >> 3;
    const int b   = blockIdx.x >> 7;          // 0..3
    const int cg2 = (blockIdx.x >> 2) & 31;   // 0..31
    const int tq  = blockIdx.x & 3;           // t-quarter (256 rows)

    if (t < 32) {
        const int c = cg2 * 32 + t;
        float v = bp[c];
        #pragma unroll
        for (int s = 0; s < KS; s++)          // 4 independent loads
            v += g_part2[(s * B + b) * C + c];
        s_rowf[t] = v;
    }
    __syncthreads();

    const float4 r = ((const float4*)s_rowf)[f4];
    float4* o4 = (float4*)out;
    const size_t base = ((size_t)b * T + tq * 256) * 256 + cg2 * 8 + f4;
    #pragma unroll
    for (int i = 0; i < 8; i++)               // rows kr, kr+32, ..., kr+224
        __stcs(&o4[base + (size_t)(kr + 32 * i) * 256], r);
}

extern "C" void kernel_launch(void* const* d_in, const int* in_sizes, int n_in,
                              void* d_out, int out_size)
{
    (void)in_sizes; (void)n_in; (void)out_size;
    const float* vf = (const float*)d_in[1];  // visual_features [B,C]
    const float* Wv = (const float*)d_in[6];
    const float* bv = (const float*)d_in[7];
    const float* Wp = (const float*)d_in[8];
    const float* bp = (const float*)d_in[9];
    float* out = (float*)d_out;

    float *p1, *p2;
    cudaGetSymbolAddress((void**)&p1, g_part1);
    cudaGetSymbolAddress((void**)&p2, g_part2);

    const dim3 g(32, KS);                     // 128 CTAs (R3's best shape)
    gemm_a<<<g, 256>>>(vf, Wv, p1);
    gemm_b<<<g, 256>>>(bv, Wp, p2);
    bcast_kernel<<<512, 256>>>(bp, out);
}

// round 14
// speedup vs baseline: 2.1523x; 2.1523x over previous
#include <cuda_runtime.h>

// CrossAttention_47502338294587 — algebraic collapse:
// out[b,t,:] = ((vf @ Wv + bv) @ Wp + bp)[b,:]  (K/V broadcast over T ->
// uniform softmax -> y == v; independent of x, Wq, Wk).
//
// R13 found the hidden cost present in EVERY gemm since R1: the smem tree
// reduce used s_red[256][B] float4 (64B row stride) -> 32 lanes hit 2 banks
// = 16-way conflict on every access of a ~20-access reduction. This version
// reduces over kr via intra-warp __shfl_xor (masks 8,16 — kr_local = lane>>3)
// + a tiny 4KB cross-warp stage. Structure otherwise = R3's best (14.8us):
// KS=4, 128-CTA gemms, 8 front-batched LDG.128, 3 launches, no atomics.

static constexpr int C  = 1024;
static constexpr int B  = 4;
static constexpr int T  = 1024;
static constexpr int KS = 4;          // k-splits: 256 k-rows per CTA

__device__ float g_part1[KS * B * C];   // 64 KB (L2-resident)
__device__ float g_part2[KS * B * C];   // 64 KB

__device__ __forceinline__ void shfl_reduce_kr(float4& a)
{
    // Butterfly over lane bits 3,4 (kr_local = lane>>3: 4 groups of 8 lanes)
    #pragma unroll
    for (int m = 8; m <= 16; m <<= 1) {
        a.x += __shfl_xor_sync(0xffffffffu, a.x, m);
        a.y += __shfl_xor_sync(0xffffffffu, a.y, m);
        a.z += __shfl_xor_sync(0xffffffffu, a.z, m);
        a.w += __shfl_xor_sync(0xffffffffu, a.w, m);
    }
}

// ---------------- K1: partials of vf @ Wv ----------------
// grid (32 cg, 4 ks) = 128 CTAs; thread: f4 = t&7, kr = t>>3, warp = t>>5.
__global__ void __launch_bounds__(256) gemm_a(
    const float* __restrict__ vf,     // [B][C]
    const float* __restrict__ W,      // [C][C]
    float* __restrict__ part)         // [KS][B][C]
{
    __shared__ float  s_in[B][256];   // 4 KB
    __shared__ float4 s2[8][8][B];    // 4 KB  [warp][f4][b]

    const int t    = threadIdx.x;
    const int f4   = t & 7;
    const int kr   = t >> 3;          // 0..31
    const int w    = t >> 5;          // warp 0..7
    const int lane = t & 31;
    const int cg   = blockIdx.x;      // 0..31
    const int ks   = blockIdx.y;      // 0..3
    const int k0   = ks * 256;

    // 8 independent full-line LDG.128, front-batched
    const float4* W4 = (const float4*)W;
    float4 wr[8];
    #pragma unroll
    for (int i = 0; i < 8; i++)
        wr[i] = W4[(size_t)(k0 + kr + 32 * i) * 256 + cg * 8 + f4];

    #pragma unroll
    for (int i = 0; i < 4; i++) {     // stage vf k-tile (1024 values)
        const int e = t + 256 * i;    // e = b*256 + kk
        s_in[e >> 8][e & 255] = vf[(e >> 8) * C + k0 + (e & 255)];
    }
    __syncthreads();

    float4 acc[B];
    #pragma unroll
    for (int b = 0; b < B; b++) {
        float4 a = make_float4(0.f, 0.f, 0.f, 0.f);
        #pragma unroll
        for (int i = 0; i < 8; i++) {
            const float s = s_in[b][kr + 32 * i];
            a.x = fmaf(s, wr[i].x, a.x);
            a.y = fmaf(s, wr[i].y, a.y);
            a.z = fmaf(s, wr[i].z, a.z);
            a.w = fmaf(s, wr[i].w, a.w);
        }
        acc[b] = a;
    }

    #pragma unroll
    for (int b = 0; b < B; b++) shfl_reduce_kr(acc[b]);  // reduce 4 kr in warp

    if (lane < 8) {                   // lanes 0-7 carry the warp partials
        #pragma unroll
        for (int b = 0; b < B; b++) s2[w][lane][b] = acc[b];
    }
    __syncthreads();

    if (t < 32) {                     // cross-warp reduce: thread = (b, f4)
        const int bb = t >> 3, ff = t & 7;
        float4 a = s2[0][ff][bb];
        #pragma unroll
        for (int j = 1; j < 8; j++) {
            const float4 o = s2[j][ff][bb];
            a.x += o.x; a.y += o.y; a.z += o.z; a.w += o.w;
        }
        ((float4*)part)[(ks * B + bb) * 256 + cg * 8 + ff] = a;
    }
}

// ------- K2: folds vv = bv + sum(part1); partials of vv @ Wp -------
__global__ void __launch_bounds__(256) gemm_b(
    const float* __restrict__ bv,     // [C]
    const float* __restrict__ W,      // Wp [C][C]
    float* __restrict__ part)         // part2 [KS][B][C]
{
    __shared__ float  s_in[B][256];
    __shared__ float4 s2[8][8][B];

    const int t    = threadIdx.x;
    const int f4   = t & 7;
    const int kr   = t >> 3;
    const int w    = t >> 5;
    const int lane = t & 31;
    const int cg   = blockIdx.x;
    const int ks   = blockIdx.y;
    const int k0   = ks * 256;

    // Wp loads first (independent of the fold below)
    const float4* W4 = (const float4*)W;
    float4 wr[8];
    #pragma unroll
    for (int i = 0; i < 8; i++)
        wr[i] = W4[(size_t)(k0 + kr + 32 * i) * 256 + cg * 8 + f4];

    #pragma unroll
    for (int i = 0; i < 4; i++) {     // fold vv k-tile: bias + 4 indep loads
        const int e  = t + 256 * i;
        const int b  = e >> 8;
        const int kk = e & 255;
        float v = bv[k0 + kk];
        #pragma unroll
        for (int s = 0; s < KS; s++)
            v += g_part1[(s * B + b) * C + k0 + kk];
        s_in[b][kk] = v;
    }
    __syncthreads();

    float4 acc[B];
    #pragma unroll
    for (int b = 0; b < B; b++) {
        float4 a = make_float4(0.f, 0.f, 0.f, 0.f);
        #pragma unroll
        for (int i = 0; i < 8; i++) {
            const float s = s_in[b][kr + 32 * i];
            a.x = fmaf(s, wr[i].x, a.x);
            a.y = fmaf(s, wr[i].y, a.y);
            a.z = fmaf(s, wr[i].z, a.z);
            a.w = fmaf(s, wr[i].w, a.w);
        }
        acc[b] = a;
    }

    #pragma unroll
    for (int b = 0; b < B; b++) shfl_reduce_kr(acc[b]);

    if (lane < 8) {
        #pragma unroll
        for (int b = 0; b < B; b++) s2[w][lane][b] = acc[b];
    }
    __syncthreads();

    if (t < 32) {
        const int bb = t >> 3, ff = t & 7;
        float4 a = s2[0][ff][bb];
        #pragma unroll
        for (int j = 1; j < 8; j++) {
            const float4 o = s2[j][ff][bb];
            a.x += o.x; a.y += o.y; a.z += o.z; a.w += o.w;
        }
        ((float4*)part)[(ks * B + bb) * 256 + cg * 8 + ff] = a;
    }
}

// ------- K3: fold row slice from part2 (+bp), broadcast-write -------
// grid 512 = (b 4) x (cg2 32) x (tq 4); CTA writes 256 rows x 32 cols.
__global__ void __launch_bounds__(256) bcast_kernel(
    const float* __restrict__ bp, float* __restrict__ out)
{
    __shared__ float s_rowf[32];

    const int t   = threadIdx.x;
    const int f4  = t & 7;
    const int kr  = t >> 3;
    const int b   = blockIdx.x >> 7;          // 0..3
    const int cg2 = (blockIdx.x >> 2) & 31;   // 0..31
    const int tq  = blockIdx.x & 3;           // t-quarter (256 rows)

    if (t < 32) {
        const int c = cg2 * 32 + t;
        float v = bp[c];
        #pragma unroll
        for (int s = 0; s < KS; s++)          // 4 independent loads
            v += g_part2[(s * B + b) * C + c];
        s_rowf[t] = v;
    }
    __syncthreads();

    const float4 r = ((const float4*)s_rowf)[f4];
    float4* o4 = (float4*)out;
    const size_t base = ((size_t)b * T + tq * 256) * 256 + cg2 * 8 + f4;
    #pragma unroll
    for (int i = 0; i < 8; i++)               // rows kr, kr+32, ..., kr+224
        o4[base + (size_t)(kr + 32 * i) * 256] = r;
}

extern "C" void kernel_launch(void* const* d_in, const int* in_sizes, int n_in,
                              void* d_out, int out_size)
{
    (void)in_sizes; (void)n_in; (void)out_size;
    const float* vf = (const float*)d_in[1];  // visual_features [B,C]
    const float* Wv = (const float*)d_in[6];
    const float* bv = (const float*)d_in[7];
    const float* Wp = (const float*)d_in[8];
    const float* bp = (const float*)d_in[9];
    float* out = (float*)d_out;

    float *p1, *p2;
    cudaGetSymbolAddress((void**)&p1, g_part1);
    cudaGetSymbolAddress((void**)&p2, g_part2);

    const dim3 g(32, KS);                     // 128 CTAs (R3's best shape)
    gemm_a<<<g, 256>>>(vf, Wv, p1);
    gemm_b<<<g, 256>>>(bv, Wp, p2);
    bcast_kernel<<<512, 256>>>(bp, out);
}

// round 15
// speedup vs baseline: 2.1955x; 1.0201x over previous
#include <cuda_runtime.h>

// CrossAttention_47502338294587 — algebraic collapse:
// out[b,t,:] = ((vf @ Wv + bv) @ Wp + bp)[b,:]  (K/V broadcast over T ->
// uniform softmax -> y == v; independent of x, Wq, Wk).
//
// Base = R14 (13.0us): 3 launches, KS=4, 128-CTA gemms, 8 front-batched
// LDG.128, shfl_xor kr-reduction (bank-conflict-free; the R1-R13 smem tree
// was 16-way conflicted). NEW in R15: gemm_a stages Wp into L2 with ONE
// scalar prefetch.global.L2 per thread (32768 threads x 128B = 4MB exactly),
// issued after the Wv loads so the fill rides gemm_a's compute tail and the
// inter-kernel gap -> gemm_b's Wp reads should be L2 hits.

static constexpr int C  = 1024;
static constexpr int B  = 4;
static constexpr int T  = 1024;
static constexpr int KS = 4;          // k-splits: 256 k-rows per CTA

__device__ float g_part1[KS * B * C];   // 64 KB (L2-resident)
__device__ float g_part2[KS * B * C];   // 64 KB

__device__ __forceinline__ void shfl_reduce_kr(float4& a)
{
    // Butterfly over lane bits 3,4 (kr_local = lane>>3: 4 groups of 8 lanes)
    #pragma unroll
    for (int m = 8; m <= 16; m <<= 1) {
        a.x += __shfl_xor_sync(0xffffffffu, a.x, m);
        a.y += __shfl_xor_sync(0xffffffffu, a.y, m);
        a.z += __shfl_xor_sync(0xffffffffu, a.z, m);
        a.w += __shfl_xor_sync(0xffffffffu, a.w, m);
    }
}

// ---------------- K1: partials of vf @ Wv (+ stage Wp into L2) --------------
// grid (32 cg, 4 ks) = 128 CTAs; thread: f4 = t&7, kr = t>>3, warp = t>>5.
__global__ void __launch_bounds__(256) gemm_a(
    const float* __restrict__ vf,     // [B][C]
    const float* __restrict__ W,      // Wv [C][C]
    const float* __restrict__ Wnext,  // Wp [C][C] — prefetched into L2
    float* __restrict__ part)         // [KS][B][C]
{
    __shared__ float  s_in[B][256];   // 4 KB
    __shared__ float4 s2[8][8][B];    // 4 KB  [warp][f4][b]

    const int t    = threadIdx.x;
    const int f4   = t & 7;
    const int kr   = t >> 3;          // 0..31
    const int w    = t >> 5;          // warp 0..7
    const int lane = t & 31;
    const int cg   = blockIdx.x;      // 0..31
    const int ks   = blockIdx.y;      // 0..3
    const int k0   = ks * 256;

    // 8 independent full-line LDG.128, front-batched
    const float4* W4 = (const float4*)W;
    float4 wr[8];
    #pragma unroll
    for (int i = 0; i < 8; i++)
        wr[i] = W4[(size_t)(k0 + kr + 32 * i) * 256 + cg * 8 + f4];

    // Stage Wp: ONE distinct 128B line per thread (32 cg * 4 ks * 256 thr
    // * 128B = 4MB = all of Wp). Issued after the Wv loads -> queues behind
    // them; fill completes during our reduction/tail + the launch gap.
    {
        const size_t line = ((size_t)(ks * 32 + cg) * 256 + t);
        asm volatile("prefetch.global.L2 [%0];"
                     :: "l"((const char*)Wnext + line * 128));
    }

    #pragma unroll
    for (int i = 0; i < 4; i++) {     // stage vf k-tile (1024 values)
        const int e = t + 256 * i;    // e = b*256 + kk
        s_in[e >> 8][e & 255] = vf[(e >> 8) * C + k0 + (e & 255)];
    }
    __syncthreads();

    float4 acc[B];
    #pragma unroll
    for (int b = 0; b < B; b++) {
        float4 a = make_float4(0.f, 0.f, 0.f, 0.f);
        #pragma unroll
        for (int i = 0; i < 8; i++) {
            const float s = s_in[b][kr + 32 * i];
            a.x = fmaf(s, wr[i].x, a.x);
            a.y = fmaf(s, wr[i].y, a.y);
            a.z = fmaf(s, wr[i].z, a.z);
            a.w = fmaf(s, wr[i].w, a.w);
        }
        acc[b] = a;
    }

    #pragma unroll
    for (int b = 0; b < B; b++) shfl_reduce_kr(acc[b]);  // reduce 4 kr in warp

    if (lane < 8) {                   // lanes 0-7 carry the warp partials
        #pragma unroll
        for (int b = 0; b < B; b++) s2[w][lane][b] = acc[b];
    }
    __syncthreads();

    if (t < 32) {                     // cross-warp reduce: thread = (b, f4)
        const int bb = t >> 3, ff = t & 7;
        float4 a = s2[0][ff][bb];
        #pragma unroll
        for (int j = 1; j < 8; j++) {
            const float4 o = s2[j][ff][bb];
            a.x += o.x; a.y += o.y; a.z += o.z; a.w += o.w;
        }
        ((float4*)part)[(ks * B + bb) * 256 + cg * 8 + ff] = a;
    }
}

// ------- K2: folds vv = bv + sum(part1); partials of vv @ Wp -------
__global__ void __launch_bounds__(256) gemm_b(
    const float* __restrict__ bv,     // [C]
    const float* __restrict__ W,      // Wp [C][C] (L2-staged by gemm_a)
    float* __restrict__ part)         // part2 [KS][B][C]
{
    __shared__ float  s_in[B][256];
    __shared__ float4 s2[8][8][B];

    const int t    = threadIdx.x;
    const int f4   = t & 7;
    const int kr   = t >> 3;
    const int w    = t >> 5;
    const int lane = t & 31;
    const int cg   = blockIdx.x;
    const int ks   = blockIdx.y;
    const int k0   = ks * 256;

    // Wp loads first (independent of the fold below)
    const float4* W4 = (const float4*)W;
    float4 wr[8];
    #pragma unroll
    for (int i = 0; i < 8; i++)
        wr[i] = W4[(size_t)(k0 + kr + 32 * i) * 256 + cg * 8 + f4];

    #pragma unroll
    for (int i = 0; i < 4; i++) {     // fold vv k-tile: bias + 4 indep loads
        const int e  = t + 256 * i;
        const int b  = e >> 8;
        const int kk = e & 255;
        float v = bv[k0 + kk];
        #pragma unroll
        for (int s = 0; s < KS; s++)
            v += g_part1[(s * B + b) * C + k0 + kk];
        s_in[b][kk] = v;
    }
    __syncthreads();

    float4 acc[B];
    #pragma unroll
    for (int b = 0; b < B; b++) {
        float4 a = make_float4(0.f, 0.f, 0.f, 0.f);
        #pragma unroll
        for (int i = 0; i < 8; i++) {
            const float s = s_in[b][kr + 32 * i];
            a.x = fmaf(s, wr[i].x, a.x);
            a.y = fmaf(s, wr[i].y, a.y);
            a.z = fmaf(s, wr[i].z, a.z);
            a.w = fmaf(s, wr[i].w, a.w);
        }
        acc[b] = a;
    }

    #pragma unroll
    for (int b = 0; b < B; b++) shfl_reduce_kr(acc[b]);

    if (lane < 8) {
        #pragma unroll
        for (int b = 0; b < B; b++) s2[w][lane][b] = acc[b];
    }
    __syncthreads();

    if (t < 32) {
        const int bb = t >> 3, ff = t & 7;
        float4 a = s2[0][ff][bb];
        #pragma unroll
        for (int j = 1; j < 8; j++) {
            const float4 o = s2[j][ff][bb];
            a.x += o.x; a.y += o.y; a.z += o.z; a.w += o.w;
        }
        ((float4*)part)[(ks * B + bb) * 256 + cg * 8 + ff] = a;
    }
}

// ------- K3: fold row slice from part2 (+bp), broadcast-write -------
// grid 512 = (b 4) x (cg2 32) x (tq 4); CTA writes 256 rows x 32 cols.
__global__ void __launch_bounds__(256) bcast_kernel(
    const float* __restrict__ bp, float* __restrict__ out)
{
    __shared__ float s_rowf[32];

    const int t   = threadIdx.x;
    const int f4  = t & 7;
    const int kr  = t >> 3;
    const int b   = blockIdx.x >> 7;          // 0..3
    const int cg2 = (blockIdx.x >> 2) & 31;   // 0..31
    const int tq  = blockIdx.x & 3;           // t-quarter (256 rows)

    if (t < 32) {
        const int c = cg2 * 32 + t;
        float v = bp[c];
        #pragma unroll
        for (int s = 0; s < KS; s++)          // 4 independent loads
            v += g_part2[(s * B + b) * C + c];
        s_rowf[t] = v;
    }
    __syncthreads();

    const float4 r = ((const float4*)s_rowf)[f4];
    float4* o4 = (float4*)out;
    const size_t base = ((size_t)b * T + tq * 256) * 256 + cg2 * 8 + f4;
    #pragma unroll
    for (int i = 0; i < 8; i++)               // rows kr, kr+32, ..., kr+224
        o4[base + (size_t)(kr + 32 * i) * 256] = r;
}

extern "C" void kernel_launch(void* const* d_in, const int* in_sizes, int n_in,
                              void* d_out, int out_size)
{
    (void)in_sizes; (void)n_in; (void)out_size;
    const float* vf = (const float*)d_in[1];  // visual_features [B,C]
    const float* Wv = (const float*)d_in[6];
    const float* bv = (const float*)d_in[7];
    const float* Wp = (const float*)d_in[8];
    const float* bp = (const float*)d_in[9];
    float* out = (float*)d_out;

    float *p1, *p2;
    cudaGetSymbolAddress((void**)&p1, g_part1);
    cudaGetSymbolAddress((void**)&p2, g_part2);

    const dim3 g(32, KS);                     // 128 CTAs
    gemm_a<<<g, 256>>>(vf, Wv, Wp, p1);
    gemm_b<<<g, 256>>>(bv, Wp, p2);
    bcast_kernel<<<512, 256>>>(bp, out);
}